// round 12
// baseline (speedup 1.0000x reference)
#include <cuda_runtime.h>

// ADDLoss — single launch; 8 lanes/element, 4 elements/warp, 128-thr blocks,
// software-pipelined point loads.
// R11 model: issued slots ~8.8us vs 14.9us runtime -> ~6us stalls, caused by
// (a) 512-block grid imbalance (3 vs 4 blocks/SM = 1.33x tail) and (b) loads
// issued right before consumers (regs=32, no front-batching). This round:
// 1024 blocks (finer balance) + explicit next-quad prefetch (load latency
// hidden under the current quad's ~21-instr compute).

#define BATCH      16384
#define NPTS       500
#define NQUADS     125                  // 4 points per quad (3 x float4)
#define NOBJ       30
#define WARPS_PB   4
#define THREADS_PB (WARPS_PB * 32)      // 128
#define ELEMS_PW   4                    // elements per warp (8 lanes each)
#define NBLOCKS    (BATCH / (WARPS_PB * ELEMS_PW))   // 1024

#define FP_SCALE     68719476736.0      // 2^36
#define INV_FP_SCALE (1.0 / 68719476736.0)

typedef unsigned long long u64;

__device__ u64 g_sum;                   // zero-init; self-resets each launch
__device__ unsigned int g_count;

__device__ __forceinline__ float sqrt_abs(float x) {
    float r; asm("sqrt.approx.f32 %0, %1;" : "=f"(r) : "f"(fabsf(x))); return r;
}

__global__ __launch_bounds__(THREADS_PB)
void addloss_kernel(const float* __restrict__ pred_r,
                    const float* __restrict__ pred_t,
                    const float* __restrict__ gt_r,
                    const float* __restrict__ gt_t,
                    const int*   __restrict__ obj_ids,
                    const float* __restrict__ points,
                    float*       __restrict__ out)
{
    const int warp_in_blk = threadIdx.x >> 5;
    const int lane        = threadIdx.x & 31;
    const int l8          = lane & 7;            // lane within element group
    const int quarter     = lane >> 3;           // which of 4 elements
    const int b = (blockIdx.x * WARPS_PB + warp_in_blk) * ELEMS_PW + quarter;

    __shared__ float sh_val[WARPS_PB];

    // ---- per-element prologue (replicated across 8 lanes; amortized 4x) ----
    int oid = obj_ids[b];
    oid = min(max(oid, 0), NOBJ - 1);
    const float4* __restrict__ pb4 =
        reinterpret_cast<const float4*>(points + (size_t)oid * (NPTS * 3));

    const float4 qp = reinterpret_cast<const float4*>(pred_r)[b];
    const float4 qg = reinterpret_cast<const float4*>(gt_r)[b];
    const float pw = qp.x, px_ = qp.y, py_ = qp.z, pz_ = qp.w;
    const float gw = qg.x, gx_ = qg.y, gy_ = qg.z, gz_ = qg.w;

    const float m00 = -2.f*(py_*py_ + pz_*pz_ - gy_*gy_ - gz_*gz_);
    const float m01 =  2.f*(px_*py_ - pw*pz_ - gx_*gy_ + gw*gz_);
    const float m02 =  2.f*(px_*pz_ + pw*py_ - gx_*gz_ - gw*gy_);
    const float m10 =  2.f*(px_*py_ + pw*pz_ - gx_*gy_ - gw*gz_);
    const float m11 = -2.f*(px_*px_ + pz_*pz_ - gx_*gx_ - gz_*gz_);
    const float m12 =  2.f*(py_*pz_ - pw*px_ - gy_*gz_ + gw*gx_);
    const float m20 =  2.f*(px_*pz_ - pw*py_ - gx_*gz_ + gw*gy_);
    const float m21 =  2.f*(py_*pz_ + pw*px_ - gy_*gz_ - gw*gx_);
    const float m22 = -2.f*(px_*px_ + py_*py_ - gx_*gx_ - gy_*gy_);

    const float tx = pred_t[3*b+0] - gt_t[3*b+0];
    const float ty = pred_t[3*b+1] - gt_t[3*b+1];
    const float tz = pred_t[3*b+2] - gt_t[3*b+2];
    const float t2 = tx*tx + ty*ty + tz*tz;

    const float s00 = m00*m00 + m10*m10 + m20*m20;
    const float s11 = m01*m01 + m11*m11 + m21*m21;
    const float s22 = m02*m02 + m12*m12 + m22*m22;
    const float s01 = 2.f*(m00*m01 + m10*m11 + m20*m21);
    const float s02 = 2.f*(m00*m02 + m10*m12 + m20*m22);
    const float s12 = 2.f*(m01*m02 + m11*m12 + m21*m22);
    const float c0  = 2.f*(m00*tx + m10*ty + m20*tz);
    const float c1  = 2.f*(m01*tx + m11*ty + m21*tz);
    const float c2  = 2.f*(m02*tx + m12*ty + m22*tz);

    float acc0 = 0.f, acc1 = 0.f;

    #define POINT_TERM(PX, PY, PZ, ACC) do {                                   \
        const float _px = (PX), _py = (PY), _pz = (PZ);                        \
        const float _U  = fmaf(s02, _pz, fmaf(s01, _py, s00*_px));             \
        const float _V  = fmaf(s12, _pz, s11*_py);                             \
        const float _W  = s22*_pz;                                             \
        const float _a2 = fmaf(_pz, _W, fmaf(_py, _V, _px*_U));                \
        const float _ln = fmaf(c0, _px, fmaf(c1, _py, fmaf(c2, _pz, t2)));     \
        const float _b2 = _a2 + _ln;                                           \
        ACC += sqrt_abs(_a2) + sqrt_abs(_b2);                                  \
    } while (0)

    #define COMPUTE_QUAD(V0, V1, V2) do {                                      \
        POINT_TERM((V0).x, (V0).y, (V0).z, acc0);                              \
        POINT_TERM((V0).w, (V1).x, (V1).y, acc1);                              \
        POINT_TERM((V1).z, (V1).w, (V2).x, acc0);                              \
        POINT_TERM((V2).y, (V2).z, (V2).w, acc1);                              \
    } while (0)

    // ---- software-pipelined loop: 15 strided quads + tail quad (l8 < 5) ----
    // quads for this lane: l8, l8+8, ..., l8+112, then (120+l8 if l8<5)
    const bool has_tail = (l8 < NQUADS - 120);   // l8 < 5
    const int  tail_q   = 120 + l8;

    float4 v0 = pb4[3*l8 + 0], v1 = pb4[3*l8 + 1], v2 = pb4[3*l8 + 2];

    #pragma unroll
    for (int k = 0; k < 15; ++k) {
        float4 n0, n1, n2;
        if (k < 14) {
            const int q = l8 + 8*(k+1);
            n0 = pb4[3*q + 0]; n1 = pb4[3*q + 1]; n2 = pb4[3*q + 2];
        } else if (has_tail) {
            n0 = pb4[3*tail_q + 0]; n1 = pb4[3*tail_q + 1]; n2 = pb4[3*tail_q + 2];
        }
        COMPUTE_QUAD(v0, v1, v2);
        v0 = n0; v1 = n1; v2 = n2;
    }
    if (has_tail)
        COMPUTE_QUAD(v0, v1, v2);

    #undef COMPUTE_QUAD
    #undef POINT_TERM

    // ---- 8-lane segment reduce (fixed order -> deterministic) ----
    float s = acc0 + acc1;
    s += __shfl_down_sync(0xffffffffu, s, 4, 8);
    s += __shfl_down_sync(0xffffffffu, s, 2, 8);
    s += __shfl_down_sync(0xffffffffu, s, 1, 8);

    // element total (valid on l8==0 lanes): mean over points + trans norm
    const float s_elem = fmaf(s, 1.0f / NPTS, sqrt_abs(t2));

    // combine the 4 element totals of this warp (fixed order)
    const float e1 = __shfl_sync(0xffffffffu, s_elem, 8);
    const float e2 = __shfl_sync(0xffffffffu, s_elem, 16);
    const float e3 = __shfl_sync(0xffffffffu, s_elem, 24);

    if (lane == 0)
        sh_val[warp_in_blk] = ((s_elem + e1) + (e2 + e3));
    __syncthreads();

    if (threadIdx.x == 0) {
        float blk = 0.f;
        #pragma unroll
        for (int w = 0; w < WARPS_PB; w++) blk += sh_val[w];

        // deterministic grid reduction: fixed-point integer atomic
        const u64 q = (u64)__double2ll_rn((double)blk * FP_SCALE);
        atomicAdd(&g_sum, q);
        __threadfence();
        const unsigned int ticket = atomicAdd(&g_count, 1u);
        if (ticket == NBLOCKS - 1) {
            const u64 total = atomicExch(&g_sum, 0ULL);  // read + reset for replay
            g_count = 0u;
            out[0] = (float)((double)total * INV_FP_SCALE * (1.0 / BATCH));
        }
    }
}

extern "C" void kernel_launch(void* const* d_in, const int* in_sizes, int n_in,
                              void* d_out, int out_size)
{
    const float* pred_r  = (const float*)d_in[0];
    const float* pred_t  = (const float*)d_in[1];
    const float* gt_r    = (const float*)d_in[2];
    const float* gt_t    = (const float*)d_in[3];
    const int*   obj_ids = (const int*)  d_in[4];
    const float* points  = (const float*)d_in[5];
    float* out = (float*)d_out;

    addloss_kernel<<<NBLOCKS, THREADS_PB>>>(pred_r, pred_t, gt_r, gt_t,
                                            obj_ids, points, out);
}

// round 13
// speedup vs baseline: 1.0152x; 1.0152x over previous
#include <cuda_runtime.h>

// ADDLoss — single launch; 16 lanes/element, 2 elements/warp, 8192 warps.
// R12 lesson: at 4096 warps occupancy (35%) starves latency hiding; prologue
// issue cost scales only with WARP count (lane redundancy is free), so 8192
// warps pays +0.5us prologue for ~2x latency coverage.
// Per point: a2 = p^T S p (Horner), b2 = a2 + c.p + t2, sqrt.approx(|x|).
// Deterministic fixed-point integer atomic reduce.

#define BATCH      16384
#define NPTS       500
#define NQUADS     125                  // 4 points per quad (3 x float4)
#define NOBJ       30
#define WARPS_PB   4
#define THREADS_PB (WARPS_PB * 32)      // 128
#define ELEMS_PW   2                    // elements per warp (16 lanes each)
#define NBLOCKS    (BATCH / (WARPS_PB * ELEMS_PW))   // 2048

#define FP_SCALE     68719476736.0      // 2^36
#define INV_FP_SCALE (1.0 / 68719476736.0)

typedef unsigned long long u64;

__device__ u64 g_sum;                   // zero-init; self-resets each launch
__device__ unsigned int g_count;

__device__ __forceinline__ float sqrt_abs(float x) {
    float r; asm("sqrt.approx.f32 %0, %1;" : "=f"(r) : "f"(fabsf(x))); return r;
}

__global__ __launch_bounds__(THREADS_PB)
void addloss_kernel(const float* __restrict__ pred_r,
                    const float* __restrict__ pred_t,
                    const float* __restrict__ gt_r,
                    const float* __restrict__ gt_t,
                    const int*   __restrict__ obj_ids,
                    const float* __restrict__ points,
                    float*       __restrict__ out)
{
    const int warp_in_blk = threadIdx.x >> 5;
    const int lane        = threadIdx.x & 31;
    const int l16         = lane & 15;           // lane within element group
    const int half        = lane >> 4;           // which of 2 elements
    const int b = (blockIdx.x * WARPS_PB + warp_in_blk) * ELEMS_PW + half;

    __shared__ float sh_val[WARPS_PB];

    // ---- per-element prologue (lane-replicated; issue cost = once per warp) ----
    int oid = obj_ids[b];
    oid = min(max(oid, 0), NOBJ - 1);
    const float4* __restrict__ pb4 =
        reinterpret_cast<const float4*>(points + (size_t)oid * (NPTS * 3));

    const float4 qp = reinterpret_cast<const float4*>(pred_r)[b];
    const float4 qg = reinterpret_cast<const float4*>(gt_r)[b];
    const float pw = qp.x, px_ = qp.y, py_ = qp.z, pz_ = qp.w;
    const float gw = qg.x, gx_ = qg.y, gy_ = qg.z, gz_ = qg.w;

    const float m00 = -2.f*(py_*py_ + pz_*pz_ - gy_*gy_ - gz_*gz_);
    const float m01 =  2.f*(px_*py_ - pw*pz_ - gx_*gy_ + gw*gz_);
    const float m02 =  2.f*(px_*pz_ + pw*py_ - gx_*gz_ - gw*gy_);
    const float m10 =  2.f*(px_*py_ + pw*pz_ - gx_*gy_ - gw*gz_);
    const float m11 = -2.f*(px_*px_ + pz_*pz_ - gx_*gx_ - gz_*gz_);
    const float m12 =  2.f*(py_*pz_ - pw*px_ - gy_*gz_ + gw*gx_);
    const float m20 =  2.f*(px_*pz_ - pw*py_ - gx_*gz_ + gw*gy_);
    const float m21 =  2.f*(py_*pz_ + pw*px_ - gy_*gz_ - gw*gx_);
    const float m22 = -2.f*(px_*px_ + py_*py_ - gx_*gx_ - gy_*gy_);

    const float tx = pred_t[3*b+0] - gt_t[3*b+0];
    const float ty = pred_t[3*b+1] - gt_t[3*b+1];
    const float tz = pred_t[3*b+2] - gt_t[3*b+2];
    const float t2 = tx*tx + ty*ty + tz*tz;

    const float s00 = m00*m00 + m10*m10 + m20*m20;
    const float s11 = m01*m01 + m11*m11 + m21*m21;
    const float s22 = m02*m02 + m12*m12 + m22*m22;
    const float s01 = 2.f*(m00*m01 + m10*m11 + m20*m21);
    const float s02 = 2.f*(m00*m02 + m10*m12 + m20*m22);
    const float s12 = 2.f*(m01*m02 + m11*m12 + m21*m22);
    const float c0  = 2.f*(m00*tx + m10*ty + m20*tz);
    const float c1  = 2.f*(m01*tx + m11*ty + m21*tz);
    const float c2  = 2.f*(m02*tx + m12*ty + m22*tz);

    float acc0 = 0.f, acc1 = 0.f;

    #define POINT_TERM(PX, PY, PZ, ACC) do {                                   \
        const float _px = (PX), _py = (PY), _pz = (PZ);                        \
        const float _U  = fmaf(s02, _pz, fmaf(s01, _py, s00*_px));             \
        const float _V  = fmaf(s12, _pz, s11*_py);                             \
        const float _W  = s22*_pz;                                             \
        const float _a2 = fmaf(_pz, _W, fmaf(_py, _V, _px*_U));                \
        const float _ln = fmaf(c0, _px, fmaf(c1, _py, fmaf(c2, _pz, t2)));     \
        const float _b2 = _a2 + _ln;                                           \
        ACC += sqrt_abs(_a2) + sqrt_abs(_b2);                                  \
    } while (0)

    #define COMPUTE_QUAD(V0, V1, V2) do {                                      \
        POINT_TERM((V0).x, (V0).y, (V0).z, acc0);                              \
        POINT_TERM((V0).w, (V1).x, (V1).y, acc1);                              \
        POINT_TERM((V1).z, (V1).w, (V2).x, acc0);                              \
        POINT_TERM((V2).y, (V2).z, (V2).w, acc1);                              \
    } while (0)

    // ---- pipelined loop: 7 strided quads + tail quad (l16 < 13) ----
    // quads for this lane: l16, l16+16, ..., l16+96, then (112+l16 if l16<13)
    const bool has_tail = (l16 < NQUADS - 112);   // l16 < 13
    const int  tail_q   = 112 + l16;

    float4 v0 = pb4[3*l16 + 0], v1 = pb4[3*l16 + 1], v2 = pb4[3*l16 + 2];

    #pragma unroll
    for (int k = 0; k < 7; ++k) {
        float4 n0, n1, n2;
        if (k < 6) {
            const int q = l16 + 16*(k+1);
            n0 = pb4[3*q + 0]; n1 = pb4[3*q + 1]; n2 = pb4[3*q + 2];
        } else if (has_tail) {
            n0 = pb4[3*tail_q + 0]; n1 = pb4[3*tail_q + 1]; n2 = pb4[3*tail_q + 2];
        }
        COMPUTE_QUAD(v0, v1, v2);
        v0 = n0; v1 = n1; v2 = n2;
    }
    if (has_tail)
        COMPUTE_QUAD(v0, v1, v2);

    #undef COMPUTE_QUAD
    #undef POINT_TERM

    // ---- 16-lane segment reduce (fixed order -> deterministic) ----
    float s = acc0 + acc1;
    s += __shfl_down_sync(0xffffffffu, s, 8, 16);
    s += __shfl_down_sync(0xffffffffu, s, 4, 16);
    s += __shfl_down_sync(0xffffffffu, s, 2, 16);
    s += __shfl_down_sync(0xffffffffu, s, 1, 16);

    // element total (valid on l16==0 lanes): mean over points + trans norm
    const float s_elem = fmaf(s, 1.0f / NPTS, sqrt_abs(t2));

    // combine the 2 element totals of this warp (fixed order)
    const float e1 = __shfl_sync(0xffffffffu, s_elem, 16);

    if (lane == 0)
        sh_val[warp_in_blk] = s_elem + e1;
    __syncthreads();

    if (threadIdx.x == 0) {
        float blk = 0.f;
        #pragma unroll
        for (int w = 0; w < WARPS_PB; w++) blk += sh_val[w];

        // deterministic grid reduction: fixed-point integer atomic
        const u64 q = (u64)__double2ll_rn((double)blk * FP_SCALE);
        atomicAdd(&g_sum, q);
        __threadfence();
        const unsigned int ticket = atomicAdd(&g_count, 1u);
        if (ticket == NBLOCKS - 1) {
            const u64 total = atomicExch(&g_sum, 0ULL);  // read + reset for replay
            g_count = 0u;
            out[0] = (float)((double)total * INV_FP_SCALE * (1.0 / BATCH));
        }
    }
}

extern "C" void kernel_launch(void* const* d_in, const int* in_sizes, int n_in,
                              void* d_out, int out_size)
{
    const float* pred_r  = (const float*)d_in[0];
    const float* pred_t  = (const float*)d_in[1];
    const float* gt_r    = (const float*)d_in[2];
    const float* gt_t    = (const float*)d_in[3];
    const int*   obj_ids = (const int*)  d_in[4];
    const float* points  = (const float*)d_in[5];
    float* out = (float*)d_out;

    addloss_kernel<<<NBLOCKS, THREADS_PB>>>(pred_r, pred_t, gt_r, gt_t,
                                            obj_ids, points, out);
}